// round 5
// baseline (speedup 1.0000x reference)
#include <cuda_runtime.h>
#include <cuda_bf16.h>

// Problem constants (from reference): N=524288, 21 residue types, 8 rigids, 24 atoms.
static constexpr int BT = 128;   // threads per block

// Shared memory layout (word offsets). All tables transposed to [component][rt]
// so divergent residue_type lanes hit 21 consecutive words -> conflict-free.
static constexpr int S_TRANS = 0;                    // 96*21 floats
static constexpr int S_RIG   = S_TRANS + 96 * 21;    // 72*21 floats
static constexpr int S_TDEP  = S_RIG   + 72 * 21;    // 8*21 ints
static constexpr int S_RDEP  = S_TDEP  + 8 * 21;     // 24*21 ints
static constexpr int S_OPR   = S_RDEP  + 24 * 21;    // 8 frames * 3 float4 * BT  (16B aligned: 16800B)
static constexpr int S_STAGE = S_OPR   + 8 * 12 * BT;// 4 warps * 72*33 floats (stride-33 pad)
static constexpr int SMEM_WORDS = S_STAGE + 4 * (72 * 33);
static constexpr int SMEM_BYTES = SMEM_WORDS * 4;    // 103,968 B -> 2 blocks/SM

__global__ void __launch_bounds__(BT)
backbone_kernel(const int* __restrict__ rtype,
                const float* __restrict__ bb,       // (N,4,3)
                const float* __restrict__ pos0,     // (N,3)
                const float* __restrict__ sc,       // (N,7,2)
                const float* __restrict__ g_trans,  // (21,8,4,3)
                const float* __restrict__ g_rig,    // (21,24,3)
                const int* __restrict__ g_tdep,     // (21,8)
                const int* __restrict__ g_rdep,     // (21,24)
                float* __restrict__ out, int nres)
{
    extern __shared__ float sm[];
    float* s_trans = sm + S_TRANS;
    float* s_rig   = sm + S_RIG;
    int*   s_tdep  = (int*)(sm + S_TDEP);
    int*   s_rdep  = (int*)(sm + S_RDEP);
    float4* s_opr  = (float4*)(sm + S_OPR);   // index: (frame*3 + quad)*BT + tid

    const int tid  = threadIdx.x;
    const int lane = tid & 31;
    const int warp = tid >> 5;
    float* stage = sm + S_STAGE + warp * (72 * 33);

    // ---- stage tables, transposed to [component][rt] ----
    for (int i = tid; i < 96 * 21; i += BT) s_trans[(i % 96) * 21 + i / 96] = g_trans[i];
    for (int i = tid; i < 72 * 21; i += BT) s_rig  [(i % 72) * 21 + i / 72] = g_rig[i];
    for (int i = tid; i < 8  * 21; i += BT) s_tdep [(i % 8 ) * 21 + i / 8 ] = g_tdep[i];
    for (int i = tid; i < 24 * 21; i += BT) s_rdep [(i % 24) * 21 + i / 24] = g_rdep[i];
    __syncthreads();

    const int n  = blockIdx.x * BT + tid;
    const int nc = (n < nres) ? n : (nres - 1);   // clamp: safe loads, stores gated later
    const int rt = rtype[nc];

    // ---- per-residue inputs (vectorized) ----
    const float4* bb4 = (const float4*)bb + (size_t)nc * 3;
    float4 b0 = bb4[0], b1 = bb4[1], b2 = bb4[2];
    // bb rotation rows
    const float Y00=b0.x, Y01=b0.y, Y02=b0.z;
    const float Y10=b0.w, Y11=b1.x, Y12=b1.y;
    const float Y20=b1.z, Y21=b1.w, Y22=b2.x;
    const float l0 = b2.y + pos0[nc*3+0];
    const float l1 = b2.z + pos0[nc*3+1];
    const float l2 = b2.w + pos0[nc*3+2];

    // ---- frame 0: combine(T[rt][0], opr0) ----
    float X[12];
    #pragma unroll
    for (int c = 0; c < 12; c++) X[c] = s_trans[c * 21 + rt];

    float o0[12];
    o0[0] = X[0]*Y00 + X[1]*Y10 + X[2]*Y20;
    o0[1] = X[0]*Y01 + X[1]*Y11 + X[2]*Y21;
    o0[2] = X[0]*Y02 + X[1]*Y12 + X[2]*Y22;
    o0[3] = X[3]*Y00 + X[4]*Y10 + X[5]*Y20;
    o0[4] = X[3]*Y01 + X[4]*Y11 + X[5]*Y21;
    o0[5] = X[3]*Y02 + X[4]*Y12 + X[5]*Y22;
    o0[6] = X[6]*Y00 + X[7]*Y10 + X[8]*Y20;
    o0[7] = X[6]*Y01 + X[7]*Y11 + X[8]*Y21;
    o0[8] = X[6]*Y02 + X[7]*Y12 + X[8]*Y22;
    o0[9]  = X[0]*l0 + X[1]*l1 + X[2]*l2 + X[9];
    o0[10] = X[3]*l0 + X[4]*l1 + X[5]*l2 + X[10];
    o0[11] = X[6]*l0 + X[7]*l1 + X[8]*l2 + X[11];

    s_opr[0*BT + tid] = make_float4(o0[0], o0[1], o0[2],  o0[3]);
    s_opr[1*BT + tid] = make_float4(o0[4], o0[5], o0[6],  o0[7]);
    s_opr[2*BT + tid] = make_float4(o0[8], o0[9], o0[10], o0[11]);

    // ---- frames 1..7: chain ----
    const float2* sc2 = (const float2*)sc + (size_t)nc * 7;
    #pragma unroll
    for (int r = 1; r < 8; r++) {
        float2 cs = sc2[r-1];
        const float cc = cs.x, ss = cs.y;

        float Xr[12];
        #pragma unroll
        for (int c = 0; c < 12; c++) Xr[c] = s_trans[(r*12 + c) * 21 + rt];

        // A = T[rt][r] composed with rot_x(c,s)  (t unchanged)
        float A0 = Xr[0], A1 = Xr[1]*cc + Xr[2]*ss, A2 = Xr[2]*cc - Xr[1]*ss;
        float A3 = Xr[3], A4 = Xr[4]*cc + Xr[5]*ss, A5 = Xr[5]*cc - Xr[4]*ss;
        float A6 = Xr[6], A7 = Xr[7]*cc + Xr[8]*ss, A8 = Xr[8]*cc - Xr[7]*ss;
        float At0 = Xr[9], At1 = Xr[10], At2 = Xr[11];

        const int dep = s_tdep[r * 21 + rt];
        float4 q0 = s_opr[(dep*3+0)*BT + tid];
        float4 q1 = s_opr[(dep*3+1)*BT + tid];
        float4 q2 = s_opr[(dep*3+2)*BT + tid];
        const float P0=q0.x,P1=q0.y,P2=q0.z,P3=q0.w,P4=q1.x,P5=q1.y,P6=q1.z,P7=q1.w,P8=q2.x;
        const float Pt0=q2.y,Pt1=q2.z,Pt2=q2.w;

        float C0 = P0*A0 + P1*A3 + P2*A6;
        float C1 = P0*A1 + P1*A4 + P2*A7;
        float C2 = P0*A2 + P1*A5 + P2*A8;
        float C3 = P3*A0 + P4*A3 + P5*A6;
        float C4 = P3*A1 + P4*A4 + P5*A7;
        float C5 = P3*A2 + P4*A5 + P5*A8;
        float C6 = P6*A0 + P7*A3 + P8*A6;
        float C7 = P6*A1 + P7*A4 + P8*A7;
        float C8 = P6*A2 + P7*A5 + P8*A8;
        float Ct0 = P0*At0 + P1*At1 + P2*At2 + Pt0;
        float Ct1 = P3*At0 + P4*At1 + P5*At2 + Pt1;
        float Ct2 = P6*At0 + P7*At1 + P8*At2 + Pt2;

        s_opr[(r*3+0)*BT + tid] = make_float4(C0, C1, C2,  C3);
        s_opr[(r*3+1)*BT + tid] = make_float4(C4, C5, C6,  C7);
        s_opr[(r*3+2)*BT + tid] = make_float4(C8, Ct0, Ct1, Ct2);
    }

    // ---- 24 atoms -> warp staging buffer (stride 33 => conflict-free both directions) ----
    #pragma unroll
    for (int a = 0; a < 24; a++) {
        const int rd = s_rdep[a * 21 + rt];
        float4 q0 = s_opr[(rd*3+0)*BT + tid];
        float4 q1 = s_opr[(rd*3+1)*BT + tid];
        float4 q2 = s_opr[(rd*3+2)*BT + tid];
        const float v0 = s_rig[(a*3+0) * 21 + rt];
        const float v1 = s_rig[(a*3+1) * 21 + rt];
        const float v2 = s_rig[(a*3+2) * 21 + rt];
        stage[(a*3+0)*33 + lane] = q0.x*v0 + q0.y*v1 + q0.z*v2 + q2.y;
        stage[(a*3+1)*33 + lane] = q0.w*v0 + q1.x*v1 + q1.y*v2 + q2.z;
        stage[(a*3+2)*33 + lane] = q1.z*v0 + q1.w*v1 + q2.x*v2 + q2.w;
    }
    __syncwarp();

    // ---- coalesced flush of atom positions: out[0 : N*72] ----
    {
        const long w0   = (long)blockIdx.x * BT + warp * 32;   // first residue of this warp
        long nrem = (long)nres - w0;
        const int cnt = (nrem >= 32) ? 32 : (nrem > 0 ? (int)nrem : 0);
        float* obase = out + w0 * 72;
        const int tot = cnt * 72;
        for (int k = lane; k < tot; k += 32) {
            const int l = k / 72;
            const int c = k - l * 72;
            obase[k] = stage[c * 33 + l];
        }
    }
    __syncwarp();

    // ---- second output: opr[:,0] (kept in registers), staged + coalesced ----
    #pragma unroll
    for (int c = 0; c < 12; c++) stage[c * 33 + lane] = o0[c];
    __syncwarp();
    {
        const long w0 = (long)blockIdx.x * BT + warp * 32;
        long nrem = (long)nres - w0;
        const int cnt = (nrem >= 32) ? 32 : (nrem > 0 ? (int)nrem : 0);
        float* obase = out + (long)nres * 72 + w0 * 12;
        const int tot = cnt * 12;
        for (int k = lane; k < tot; k += 32) {
            const int l = k / 12;
            const int c = k - l * 12;
            obase[k] = stage[c * 33 + l];
        }
    }
}

extern "C" void kernel_launch(void* const* d_in, const int* in_sizes, int n_in,
                              void* d_out, int out_size)
{
    const int*   rtype   = (const int*)  d_in[0];
    const float* bb      = (const float*)d_in[1];
    const float* pos0    = (const float*)d_in[2];
    const float* sc      = (const float*)d_in[3];
    const float* g_trans = (const float*)d_in[4];
    const float* g_rig   = (const float*)d_in[5];
    const int*   g_tdep  = (const int*)  d_in[6];
    const int*   g_rdep  = (const int*)  d_in[7];
    float* out = (float*)d_out;

    const int nres = in_sizes[0];

    // Opt-in to >48KB dynamic smem (host-side attribute, not a stream op; capture-safe).
    cudaFuncSetAttribute(backbone_kernel,
                         cudaFuncAttributeMaxDynamicSharedMemorySize, SMEM_BYTES);

    const int grid = (nres + BT - 1) / BT;
    backbone_kernel<<<grid, BT, SMEM_BYTES>>>(rtype, bb, pos0, sc,
                                              g_trans, g_rig, g_tdep, g_rdep,
                                              out, nres);
}

// round 6
// speedup vs baseline: 1.2167x; 1.2167x over previous
#include <cuda_runtime.h>
#include <cuda_bf16.h>

// N=524288 residues, 21 residue types, 8 rigid frames, 24 atoms.
static constexpr int BT  = 128;      // threads per block (1 thread = 1 residue for frame build)
static constexpr int PAD = BT + 1;   // float4 row stride for s_opr (bank-conflict padding)

// Shared memory layout (word offsets)
static constexpr int S_TRANS = 0;                    // 96*21 floats (transposed [comp][rt])
static constexpr int S_RIG   = S_TRANS + 96 * 21;    // 72*21 floats
static constexpr int S_RT    = S_RIG   + 72 * 21;    // BT ints
static constexpr int S_DEP8  = S_RT    + BT;         // bytes: tdep 8*21 + rdep 24*21 = 672 B = 168 words
static constexpr int S_OPR   = S_DEP8  + 168;        // 24 quads * PAD float4  (word off 3824 -> 16B aligned)
static constexpr int SMEM_WORDS = S_OPR + 24 * PAD * 4;
static constexpr int SMEM_BYTES = SMEM_WORDS * 4;    // 64,832 B -> 3 blocks/SM = 12 warps

__global__ void __launch_bounds__(BT)
backbone_kernel(const int* __restrict__ rtype,
                const float* __restrict__ bb,       // (N,4,3)
                const float* __restrict__ pos0,     // (N,3)
                const float* __restrict__ sc,       // (N,7,2)
                const float* __restrict__ g_trans,  // (21,8,4,3)
                const float* __restrict__ g_rig,    // (21,24,3)
                const int* __restrict__ g_tdep,     // (21,8)
                const int* __restrict__ g_rdep,     // (21,24)
                float* __restrict__ out, int nres)
{
    extern __shared__ float sm[];
    float* s_trans = sm + S_TRANS;
    float* s_rig   = sm + S_RIG;
    int*   s_rt    = (int*)(sm + S_RT);
    unsigned char* s_tdep8 = (unsigned char*)(sm + S_DEP8);
    unsigned char* s_rdep8 = s_tdep8 + 8 * 21;
    float4* s_opr  = (float4*)(sm + S_OPR);   // index: (frame*3 + quad)*PAD + tid

    const int tid  = threadIdx.x;
    const int lane = tid & 31;
    const int warp = tid >> 5;

    // ---- stage tables, transposed to [component][rt] (stride 21 -> conflict-free) ----
    for (int i = tid; i < 96 * 21; i += BT) s_trans[(i % 96) * 21 + i / 96] = g_trans[i];
    for (int i = tid; i < 72 * 21; i += BT) s_rig  [(i % 72) * 21 + i / 72] = g_rig[i];
    for (int i = tid; i < 8  * 21; i += BT) s_tdep8[(i % 8 ) * 21 + i / 8 ] = (unsigned char)g_tdep[i];
    for (int i = tid; i < 24 * 21; i += BT) s_rdep8[(i % 24) * 21 + i / 24] = (unsigned char)g_rdep[i];
    __syncthreads();

    const int n  = blockIdx.x * BT + tid;
    const int nc = (n < nres) ? n : (nres - 1);   // clamp: safe loads; stores gated later
    const int rt = rtype[nc];
    s_rt[tid] = rt;

    // ---- per-residue inputs (vectorized) ----
    const float4* bb4 = (const float4*)bb + (size_t)nc * 3;
    float4 b0 = bb4[0], b1 = bb4[1], b2 = bb4[2];
    const float Y00=b0.x, Y01=b0.y, Y02=b0.z;
    const float Y10=b0.w, Y11=b1.x, Y12=b1.y;
    const float Y20=b1.z, Y21=b1.w, Y22=b2.x;
    const float l0 = b2.y + pos0[nc*3+0];
    const float l1 = b2.z + pos0[nc*3+1];
    const float l2 = b2.w + pos0[nc*3+2];

    // ---- frame 0: combine(T[rt][0], opr0) ----
    float X[12];
    #pragma unroll
    for (int c = 0; c < 12; c++) X[c] = s_trans[c * 21 + rt];

    float o0[12];
    o0[0] = X[0]*Y00 + X[1]*Y10 + X[2]*Y20;
    o0[1] = X[0]*Y01 + X[1]*Y11 + X[2]*Y21;
    o0[2] = X[0]*Y02 + X[1]*Y12 + X[2]*Y22;
    o0[3] = X[3]*Y00 + X[4]*Y10 + X[5]*Y20;
    o0[4] = X[3]*Y01 + X[4]*Y11 + X[5]*Y21;
    o0[5] = X[3]*Y02 + X[4]*Y12 + X[5]*Y22;
    o0[6] = X[6]*Y00 + X[7]*Y10 + X[8]*Y20;
    o0[7] = X[6]*Y01 + X[7]*Y11 + X[8]*Y21;
    o0[8] = X[6]*Y02 + X[7]*Y12 + X[8]*Y22;
    o0[9]  = X[0]*l0 + X[1]*l1 + X[2]*l2 + X[9];
    o0[10] = X[3]*l0 + X[4]*l1 + X[5]*l2 + X[10];
    o0[11] = X[6]*l0 + X[7]*l1 + X[8]*l2 + X[11];

    s_opr[0*PAD + tid] = make_float4(o0[0], o0[1], o0[2],  o0[3]);
    s_opr[1*PAD + tid] = make_float4(o0[4], o0[5], o0[6],  o0[7]);
    s_opr[2*PAD + tid] = make_float4(o0[8], o0[9], o0[10], o0[11]);

    // ---- frames 1..7: dependency chain (per-thread; reads own column only) ----
    const float2* sc2 = (const float2*)sc + (size_t)nc * 7;
    #pragma unroll
    for (int r = 1; r < 8; r++) {
        float2 cs = sc2[r-1];
        const float cc = cs.x, ss = cs.y;

        float Xr[12];
        #pragma unroll
        for (int c = 0; c < 12; c++) Xr[c] = s_trans[(r*12 + c) * 21 + rt];

        // A = T[rt][r] composed with rot_x(c,s)  (translation unchanged)
        float A0 = Xr[0], A1 = Xr[1]*cc + Xr[2]*ss, A2 = Xr[2]*cc - Xr[1]*ss;
        float A3 = Xr[3], A4 = Xr[4]*cc + Xr[5]*ss, A5 = Xr[5]*cc - Xr[4]*ss;
        float A6 = Xr[6], A7 = Xr[7]*cc + Xr[8]*ss, A8 = Xr[8]*cc - Xr[7]*ss;
        float At0 = Xr[9], At1 = Xr[10], At2 = Xr[11];

        const int dep = (int)s_tdep8[r * 21 + rt];
        float4 q0 = s_opr[(dep*3+0)*PAD + tid];
        float4 q1 = s_opr[(dep*3+1)*PAD + tid];
        float4 q2 = s_opr[(dep*3+2)*PAD + tid];
        const float P0=q0.x,P1=q0.y,P2=q0.z,P3=q0.w,P4=q1.x,P5=q1.y,P6=q1.z,P7=q1.w,P8=q2.x;
        const float Pt0=q2.y,Pt1=q2.z,Pt2=q2.w;

        float C0 = P0*A0 + P1*A3 + P2*A6;
        float C1 = P0*A1 + P1*A4 + P2*A7;
        float C2 = P0*A2 + P1*A5 + P2*A8;
        float C3 = P3*A0 + P4*A3 + P5*A6;
        float C4 = P3*A1 + P4*A4 + P5*A7;
        float C5 = P3*A2 + P4*A5 + P5*A8;
        float C6 = P6*A0 + P7*A3 + P8*A6;
        float C7 = P6*A1 + P7*A4 + P8*A7;
        float C8 = P6*A2 + P7*A5 + P8*A8;
        float Ct0 = P0*At0 + P1*At1 + P2*At2 + Pt0;
        float Ct1 = P3*At0 + P4*At1 + P5*At2 + Pt1;
        float Ct2 = P6*At0 + P7*At1 + P8*At2 + Pt2;

        s_opr[(r*3+0)*PAD + tid] = make_float4(C0, C1, C2,  C3);
        s_opr[(r*3+1)*PAD + tid] = make_float4(C4, C5, C6,  C7);
        s_opr[(r*3+2)*PAD + tid] = make_float4(C8, Ct0, Ct1, Ct2);
    }

    __syncwarp();   // cooperative phase reads frames of the whole warp (same warp produced them)

    // ---- warp-cooperative atom phase: tasks k = it*32+lane over (rho=k/24, a=k%24) ----
    // Output address = warpbase*72 + 3k + j  -> 32 lanes cover a contiguous 384B window.
    {
        const int wbase = warp * 32;
        const long resBase = (long)blockIdx.x * BT + wbase;
        float* owarp = out + resBase * 72;

        int a   = (lane < 24) ? lane : lane - 24;
        int rho = (lane < 24) ? 0 : 1;

        #pragma unroll
        for (int it = 0; it < 24; ++it) {
            const int trho = wbase + rho;
            const int rtl  = s_rt[trho];
            const int rd   = (int)s_rdep8[a * 21 + rtl];
            float4 q0 = s_opr[(rd*3+0)*PAD + trho];
            float4 q1 = s_opr[(rd*3+1)*PAD + trho];
            float4 q2 = s_opr[(rd*3+2)*PAD + trho];
            const float v0 = s_rig[(a*3+0) * 21 + rtl];
            const float v1 = s_rig[(a*3+1) * 21 + rtl];
            const float v2 = s_rig[(a*3+2) * 21 + rtl];
            if (resBase + rho < (long)nres) {
                float* p = owarp + rho * 72 + a * 3;
                p[0] = q0.x*v0 + q0.y*v1 + q0.z*v2 + q2.y;
                p[1] = q0.w*v0 + q1.x*v1 + q1.y*v2 + q2.z;
                p[2] = q1.z*v0 + q1.w*v1 + q2.x*v2 + q2.w;
            }
            // advance k by 32: a += 8 (wrap 24), rho += 1 (+1 extra on wrap)
            a += 8; rho += 1;
            if (a >= 24) { a -= 24; rho += 2 - 1; rho += 0; a = a; rho = rho + 1 - 1 + 1 - 1; }
            if (false) {}
        }
    }

    // ---- second output: opr[:,0] (read from smem frame 0), coalesced ----
    {
        const int wbase = warp * 32;
        const long resBase = (long)blockIdx.x * BT + wbase;
        long rem = (long)nres - resBase;
        const int cnt = (rem >= 32) ? 32 : (rem > 0 ? (int)rem : 0);
        float* o2 = out + (long)nres * 72 + resBase * 12;
        const int tot = cnt * 12;
        for (int k = lane; k < tot; k += 32) {
            const int l = k / 12;
            const int c = k - l * 12;
            const float* sp = (const float*)&s_opr[(c >> 2) * PAD + wbase + l];
            o2[k] = sp[c & 3];
        }
    }
}

extern "C" void kernel_launch(void* const* d_in, const int* in_sizes, int n_in,
                              void* d_out, int out_size)
{
    const int*   rtype   = (const int*)  d_in[0];
    const float* bb      = (const float*)d_in[1];
    const float* pos0    = (const float*)d_in[2];
    const float* sc      = (const float*)d_in[3];
    const float* g_trans = (const float*)d_in[4];
    const float* g_rig   = (const float*)d_in[5];
    const int*   g_tdep  = (const int*)  d_in[6];
    const int*   g_rdep  = (const int*)  d_in[7];
    float* out = (float*)d_out;

    const int nres = in_sizes[0];

    cudaFuncSetAttribute(backbone_kernel,
                         cudaFuncAttributeMaxDynamicSharedMemorySize, SMEM_BYTES);

    const int grid = (nres + BT - 1) / BT;
    backbone_kernel<<<grid, BT, SMEM_BYTES>>>(rtype, bb, pos0, sc,
                                              g_trans, g_rig, g_tdep, g_rdep,
                                              out, nres);
}

// round 7
// speedup vs baseline: 1.2233x; 1.0054x over previous
#include <cuda_runtime.h>
#include <cuda_bf16.h>

// N=524288 residues, 21 residue types, 8 rigid frames, 24 atoms.
static constexpr int BT  = 128;      // threads per block (1 thread = 1 residue for frame build)
static constexpr int PAD = BT + 1;   // float4 row stride for s_opr (bank-conflict padding)

// Shared memory layout (word offsets)
static constexpr int S_TRANS = 0;                    // 96*21 floats (transposed [comp][rt])
static constexpr int S_RIG   = S_TRANS + 96 * 21;    // 72*21 floats
static constexpr int S_RT    = S_RIG   + 72 * 21;    // BT ints
static constexpr int S_DEP8  = S_RT    + BT;         // bytes: tdep 8*21 + rdep 24*21 = 672 B = 168 words
static constexpr int S_OPR   = S_DEP8  + 168;        // 24 quads * PAD float4  (word off 3824 -> 16B aligned)
static constexpr int SMEM_WORDS = S_OPR + 24 * PAD * 4;
static constexpr int SMEM_BYTES = SMEM_WORDS * 4;    // 64,832 B -> 3 blocks/SM = 12 warps

__global__ void __launch_bounds__(BT)
backbone_kernel(const int* __restrict__ rtype,
                const float* __restrict__ bb,       // (N,4,3)
                const float* __restrict__ pos0,     // (N,3)
                const float* __restrict__ sc,       // (N,7,2)
                const float* __restrict__ g_trans,  // (21,8,4,3)
                const float* __restrict__ g_rig,    // (21,24,3)
                const int* __restrict__ g_tdep,     // (21,8)
                const int* __restrict__ g_rdep,     // (21,24)
                float* __restrict__ out, int nres)
{
    extern __shared__ float sm[];
    float* s_trans = sm + S_TRANS;
    float* s_rig   = sm + S_RIG;
    int*   s_rt    = (int*)(sm + S_RT);
    unsigned char* s_tdep8 = (unsigned char*)(sm + S_DEP8);
    unsigned char* s_rdep8 = s_tdep8 + 8 * 21;
    float4* s_opr  = (float4*)(sm + S_OPR);   // index: (frame*3 + quad)*PAD + tid

    const int tid  = threadIdx.x;
    const int lane = tid & 31;
    const int warp = tid >> 5;

    // ---- stage tables, transposed to [component][rt] (stride 21 -> conflict-free) ----
    for (int i = tid; i < 96 * 21; i += BT) s_trans[(i % 96) * 21 + i / 96] = g_trans[i];
    for (int i = tid; i < 72 * 21; i += BT) s_rig  [(i % 72) * 21 + i / 72] = g_rig[i];
    for (int i = tid; i < 8  * 21; i += BT) s_tdep8[(i % 8 ) * 21 + i / 8 ] = (unsigned char)g_tdep[i];
    for (int i = tid; i < 24 * 21; i += BT) s_rdep8[(i % 24) * 21 + i / 24] = (unsigned char)g_rdep[i];
    __syncthreads();

    const int n  = blockIdx.x * BT + tid;
    const int nc = (n < nres) ? n : (nres - 1);   // clamp: safe loads; stores gated later
    const int rt = rtype[nc];
    s_rt[tid] = rt;

    // ---- per-residue inputs (vectorized) ----
    const float4* bb4 = (const float4*)bb + (size_t)nc * 3;
    float4 b0 = bb4[0], b1 = bb4[1], b2 = bb4[2];
    const float Y00=b0.x, Y01=b0.y, Y02=b0.z;
    const float Y10=b0.w, Y11=b1.x, Y12=b1.y;
    const float Y20=b1.z, Y21=b1.w, Y22=b2.x;
    const float l0 = b2.y + pos0[nc*3+0];
    const float l1 = b2.z + pos0[nc*3+1];
    const float l2 = b2.w + pos0[nc*3+2];

    // ---- frame 0: combine(T[rt][0], opr0) ----
    float X[12];
    #pragma unroll
    for (int c = 0; c < 12; c++) X[c] = s_trans[c * 21 + rt];

    float o0[12];
    o0[0] = X[0]*Y00 + X[1]*Y10 + X[2]*Y20;
    o0[1] = X[0]*Y01 + X[1]*Y11 + X[2]*Y21;
    o0[2] = X[0]*Y02 + X[1]*Y12 + X[2]*Y22;
    o0[3] = X[3]*Y00 + X[4]*Y10 + X[5]*Y20;
    o0[4] = X[3]*Y01 + X[4]*Y11 + X[5]*Y21;
    o0[5] = X[3]*Y02 + X[4]*Y12 + X[5]*Y22;
    o0[6] = X[6]*Y00 + X[7]*Y10 + X[8]*Y20;
    o0[7] = X[6]*Y01 + X[7]*Y11 + X[8]*Y21;
    o0[8] = X[6]*Y02 + X[7]*Y12 + X[8]*Y22;
    o0[9]  = X[0]*l0 + X[1]*l1 + X[2]*l2 + X[9];
    o0[10] = X[3]*l0 + X[4]*l1 + X[5]*l2 + X[10];
    o0[11] = X[6]*l0 + X[7]*l1 + X[8]*l2 + X[11];

    s_opr[0*PAD + tid] = make_float4(o0[0], o0[1], o0[2],  o0[3]);
    s_opr[1*PAD + tid] = make_float4(o0[4], o0[5], o0[6],  o0[7]);
    s_opr[2*PAD + tid] = make_float4(o0[8], o0[9], o0[10], o0[11]);

    // ---- frames 1..7: dependency chain (per-thread; reads own column only) ----
    const float2* sc2 = (const float2*)sc + (size_t)nc * 7;
    #pragma unroll
    for (int r = 1; r < 8; r++) {
        float2 cs = sc2[r-1];
        const float cc = cs.x, ss = cs.y;

        float Xr[12];
        #pragma unroll
        for (int c = 0; c < 12; c++) Xr[c] = s_trans[(r*12 + c) * 21 + rt];

        // A = T[rt][r] composed with rot_x(c,s)  (translation unchanged)
        float A0 = Xr[0], A1 = Xr[1]*cc + Xr[2]*ss, A2 = Xr[2]*cc - Xr[1]*ss;
        float A3 = Xr[3], A4 = Xr[4]*cc + Xr[5]*ss, A5 = Xr[5]*cc - Xr[4]*ss;
        float A6 = Xr[6], A7 = Xr[7]*cc + Xr[8]*ss, A8 = Xr[8]*cc - Xr[7]*ss;
        float At0 = Xr[9], At1 = Xr[10], At2 = Xr[11];

        const int dep = (int)s_tdep8[r * 21 + rt];
        float4 q0 = s_opr[(dep*3+0)*PAD + tid];
        float4 q1 = s_opr[(dep*3+1)*PAD + tid];
        float4 q2 = s_opr[(dep*3+2)*PAD + tid];
        const float P0=q0.x,P1=q0.y,P2=q0.z,P3=q0.w,P4=q1.x,P5=q1.y,P6=q1.z,P7=q1.w,P8=q2.x;
        const float Pt0=q2.y,Pt1=q2.z,Pt2=q2.w;

        float C0 = P0*A0 + P1*A3 + P2*A6;
        float C1 = P0*A1 + P1*A4 + P2*A7;
        float C2 = P0*A2 + P1*A5 + P2*A8;
        float C3 = P3*A0 + P4*A3 + P5*A6;
        float C4 = P3*A1 + P4*A4 + P5*A7;
        float C5 = P3*A2 + P4*A5 + P5*A8;
        float C6 = P6*A0 + P7*A3 + P8*A6;
        float C7 = P6*A1 + P7*A4 + P8*A7;
        float C8 = P6*A2 + P7*A5 + P8*A8;
        float Ct0 = P0*At0 + P1*At1 + P2*At2 + Pt0;
        float Ct1 = P3*At0 + P4*At1 + P5*At2 + Pt1;
        float Ct2 = P6*At0 + P7*At1 + P8*At2 + Pt2;

        s_opr[(r*3+0)*PAD + tid] = make_float4(C0, C1, C2,  C3);
        s_opr[(r*3+1)*PAD + tid] = make_float4(C4, C5, C6,  C7);
        s_opr[(r*3+2)*PAD + tid] = make_float4(C8, Ct0, Ct1, Ct2);
    }

    __syncwarp();   // cooperative phase reads frames of the whole warp (same warp produced them)

    // ---- warp-cooperative atom phase: tasks k = it*32+lane over (rho=k/24, a=k%24) ----
    // Output address = warpbase*72 + 3k + j  -> 32 lanes cover a contiguous 384B window.
    {
        const int wbase = warp * 32;
        const long resBase = (long)blockIdx.x * BT + wbase;
        float* owarp = out + resBase * 72;

        int a   = (lane < 24) ? lane : lane - 24;
        int rho = (lane < 24) ? 0 : 1;

        #pragma unroll
        for (int it = 0; it < 24; ++it) {
            const int trho = wbase + rho;
            const int rtl  = s_rt[trho];
            const int rd   = (int)s_rdep8[a * 21 + rtl];
            float4 q0 = s_opr[(rd*3+0)*PAD + trho];
            float4 q1 = s_opr[(rd*3+1)*PAD + trho];
            float4 q2 = s_opr[(rd*3+2)*PAD + trho];
            const float v0 = s_rig[(a*3+0) * 21 + rtl];
            const float v1 = s_rig[(a*3+1) * 21 + rtl];
            const float v2 = s_rig[(a*3+2) * 21 + rtl];
            if (resBase + rho < (long)nres) {
                float* p = owarp + rho * 72 + a * 3;
                p[0] = q0.x*v0 + q0.y*v1 + q0.z*v2 + q2.y;
                p[1] = q0.w*v0 + q1.x*v1 + q1.y*v2 + q2.z;
                p[2] = q1.z*v0 + q1.w*v1 + q2.x*v2 + q2.w;
            }
            // advance k by 32: a += 8 (wrap 24), rho += 1 (+1 extra on wrap)
            a += 8; rho += 1;
            if (a >= 24) { a -= 24; rho += 2 - 1; rho += 0; a = a; rho = rho + 1 - 1 + 1 - 1; }
            if (false) {}
        }
    }

    // ---- second output: opr[:,0] (read from smem frame 0), coalesced ----
    {
        const int wbase = warp * 32;
        const long resBase = (long)blockIdx.x * BT + wbase;
        long rem = (long)nres - resBase;
        const int cnt = (rem >= 32) ? 32 : (rem > 0 ? (int)rem : 0);
        float* o2 = out + (long)nres * 72 + resBase * 12;
        const int tot = cnt * 12;
        for (int k = lane; k < tot; k += 32) {
            const int l = k / 12;
            const int c = k - l * 12;
            const float* sp = (const float*)&s_opr[(c >> 2) * PAD + wbase + l];
            o2[k] = sp[c & 3];
        }
    }
}

extern "C" void kernel_launch(void* const* d_in, const int* in_sizes, int n_in,
                              void* d_out, int out_size)
{
    const int*   rtype   = (const int*)  d_in[0];
    const float* bb      = (const float*)d_in[1];
    const float* pos0    = (const float*)d_in[2];
    const float* sc      = (const float*)d_in[3];
    const float* g_trans = (const float*)d_in[4];
    const float* g_rig   = (const float*)d_in[5];
    const int*   g_tdep  = (const int*)  d_in[6];
    const int*   g_rdep  = (const int*)  d_in[7];
    float* out = (float*)d_out;

    const int nres = in_sizes[0];

    cudaFuncSetAttribute(backbone_kernel,
                         cudaFuncAttributeMaxDynamicSharedMemorySize, SMEM_BYTES);

    const int grid = (nres + BT - 1) / BT;
    backbone_kernel<<<grid, BT, SMEM_BYTES>>>(rtype, bb, pos0, sc,
                                              g_trans, g_rig, g_tdep, g_rdep,
                                              out, nres);
}

// round 8
// speedup vs baseline: 1.5731x; 1.2859x over previous
#include <cuda_runtime.h>
#include <cuda_bf16.h>

// N=524288 residues, 21 residue types, 8 rigid frames, 24 atoms.
static constexpr int BT  = 256;      // threads per block (1 thread = 1 residue for frame build)
static constexpr int PAD = BT + 1;   // float4 row stride for s_opr (bank-conflict padding)

// Shared memory layout (word offsets)
static constexpr int S_TRANS = 0;                    // 96*21 floats (transposed [comp][rt])
static constexpr int S_RIG   = S_TRANS + 96 * 21;    // 72*21 floats
static constexpr int S_RT    = S_RIG   + 72 * 21;    // BT ints
static constexpr int S_DEP8  = S_RT    + BT;         // bytes: tdep 8*21 + rdep 24*21 = 672 B = 168 words
static constexpr int S_OPR   = S_DEP8  + 168;        // 24 quads * PAD float4 (word offset 16B-aligned)
static constexpr int SMEM_WORDS = S_OPR + 24 * PAD * 4;
static constexpr int SMEM_BYTES = SMEM_WORDS * 4;    // ~114.5 KB -> 2 blocks/SM = 16 warps

static_assert(S_OPR % 4 == 0, "s_opr must be 16B aligned");

__global__ void __launch_bounds__(BT)
backbone_kernel(const int* __restrict__ rtype,
                const float* __restrict__ bb,       // (N,4,3)
                const float* __restrict__ pos0,     // (N,3)
                const float* __restrict__ sc,       // (N,7,2)
                const float* __restrict__ g_trans,  // (21,8,4,3)
                const float* __restrict__ g_rig,    // (21,24,3)
                const int* __restrict__ g_tdep,     // (21,8)
                const int* __restrict__ g_rdep,     // (21,24)
                float* __restrict__ out, int nres)
{
    extern __shared__ float sm[];
    float* s_trans = sm + S_TRANS;
    float* s_rig   = sm + S_RIG;
    int*   s_rt    = (int*)(sm + S_RT);
    unsigned char* s_tdep8 = (unsigned char*)(sm + S_DEP8);
    unsigned char* s_rdep8 = s_tdep8 + 8 * 21;
    float4* s_opr  = (float4*)(sm + S_OPR);   // index: (frame*3 + quad)*PAD + tid

    const int tid  = threadIdx.x;
    const int lane = tid & 31;
    const int warp = tid >> 5;

    // ---- stage tables, transposed to [component][rt] (stride 21 -> conflict-free) ----
    for (int i = tid; i < 96 * 21; i += BT) s_trans[(i % 96) * 21 + i / 96] = g_trans[i];
    for (int i = tid; i < 72 * 21; i += BT) s_rig  [(i % 72) * 21 + i / 72] = g_rig[i];
    for (int i = tid; i < 8  * 21; i += BT) s_tdep8[(i % 8 ) * 21 + i / 8 ] = (unsigned char)g_tdep[i];
    for (int i = tid; i < 24 * 21; i += BT) s_rdep8[(i % 24) * 21 + i / 24] = (unsigned char)g_rdep[i];
    __syncthreads();

    const int n  = blockIdx.x * BT + tid;
    const int nc = (n < nres) ? n : (nres - 1);   // clamp: safe loads; stores gated later
    const int rt = rtype[nc];
    s_rt[tid] = rt;

    // ---- per-residue inputs (vectorized); prefetch ALL before the chain ----
    const float4* bb4 = (const float4*)bb + (size_t)nc * 3;
    float4 b0 = bb4[0], b1 = bb4[1], b2 = bb4[2];

    const float2* sc2 = (const float2*)sc + (size_t)nc * 7;
    float2 cs[7];
    #pragma unroll
    for (int r = 0; r < 7; r++) cs[r] = sc2[r];   // hoists gmem latency out of the serial chain

    const float p0x = pos0[nc*3+0], p0y = pos0[nc*3+1], p0z = pos0[nc*3+2];

    const float Y00=b0.x, Y01=b0.y, Y02=b0.z;
    const float Y10=b0.w, Y11=b1.x, Y12=b1.y;
    const float Y20=b1.z, Y21=b1.w, Y22=b2.x;
    const float l0 = b2.y + p0x;
    const float l1 = b2.z + p0y;
    const float l2 = b2.w + p0z;

    // ---- frame 0: combine(T[rt][0], opr0) ----
    float X[12];
    #pragma unroll
    for (int c = 0; c < 12; c++) X[c] = s_trans[c * 21 + rt];

    float o0[12];
    o0[0] = X[0]*Y00 + X[1]*Y10 + X[2]*Y20;
    o0[1] = X[0]*Y01 + X[1]*Y11 + X[2]*Y21;
    o0[2] = X[0]*Y02 + X[1]*Y12 + X[2]*Y22;
    o0[3] = X[3]*Y00 + X[4]*Y10 + X[5]*Y20;
    o0[4] = X[3]*Y01 + X[4]*Y11 + X[5]*Y21;
    o0[5] = X[3]*Y02 + X[4]*Y12 + X[5]*Y22;
    o0[6] = X[6]*Y00 + X[7]*Y10 + X[8]*Y20;
    o0[7] = X[6]*Y01 + X[7]*Y11 + X[8]*Y21;
    o0[8] = X[6]*Y02 + X[7]*Y12 + X[8]*Y22;
    o0[9]  = X[0]*l0 + X[1]*l1 + X[2]*l2 + X[9];
    o0[10] = X[3]*l0 + X[4]*l1 + X[5]*l2 + X[10];
    o0[11] = X[6]*l0 + X[7]*l1 + X[8]*l2 + X[11];

    s_opr[0*PAD + tid] = make_float4(o0[0], o0[1], o0[2],  o0[3]);
    s_opr[1*PAD + tid] = make_float4(o0[4], o0[5], o0[6],  o0[7]);
    s_opr[2*PAD + tid] = make_float4(o0[8], o0[9], o0[10], o0[11]);

    // ---- frames 1..7: dependency chain (per-thread; reads own column only) ----
    #pragma unroll
    for (int r = 1; r < 8; r++) {
        const float cc = cs[r-1].x, ss = cs[r-1].y;

        float Xr[12];
        #pragma unroll
        for (int c = 0; c < 12; c++) Xr[c] = s_trans[(r*12 + c) * 21 + rt];

        // A = T[rt][r] composed with rot_x(c,s)  (translation unchanged)
        float A0 = Xr[0], A1 = Xr[1]*cc + Xr[2]*ss, A2 = Xr[2]*cc - Xr[1]*ss;
        float A3 = Xr[3], A4 = Xr[4]*cc + Xr[5]*ss, A5 = Xr[5]*cc - Xr[4]*ss;
        float A6 = Xr[6], A7 = Xr[7]*cc + Xr[8]*ss, A8 = Xr[8]*cc - Xr[7]*ss;
        float At0 = Xr[9], At1 = Xr[10], At2 = Xr[11];

        const int dep = (int)s_tdep8[r * 21 + rt];
        float4 q0 = s_opr[(dep*3+0)*PAD + tid];
        float4 q1 = s_opr[(dep*3+1)*PAD + tid];
        float4 q2 = s_opr[(dep*3+2)*PAD + tid];
        const float P0=q0.x,P1=q0.y,P2=q0.z,P3=q0.w,P4=q1.x,P5=q1.y,P6=q1.z,P7=q1.w,P8=q2.x;
        const float Pt0=q2.y,Pt1=q2.z,Pt2=q2.w;

        float C0 = P0*A0 + P1*A3 + P2*A6;
        float C1 = P0*A1 + P1*A4 + P2*A7;
        float C2 = P0*A2 + P1*A5 + P2*A8;
        float C3 = P3*A0 + P4*A3 + P5*A6;
        float C4 = P3*A1 + P4*A4 + P5*A7;
        float C5 = P3*A2 + P4*A5 + P5*A8;
        float C6 = P6*A0 + P7*A3 + P8*A6;
        float C7 = P6*A1 + P7*A4 + P8*A7;
        float C8 = P6*A2 + P7*A5 + P8*A8;
        float Ct0 = P0*At0 + P1*At1 + P2*At2 + Pt0;
        float Ct1 = P3*At0 + P4*At1 + P5*At2 + Pt1;
        float Ct2 = P6*At0 + P7*At1 + P8*At2 + Pt2;

        s_opr[(r*3+0)*PAD + tid] = make_float4(C0, C1, C2,  C3);
        s_opr[(r*3+1)*PAD + tid] = make_float4(C4, C5, C6,  C7);
        s_opr[(r*3+2)*PAD + tid] = make_float4(C8, Ct0, Ct1, Ct2);
    }

    __syncwarp();   // cooperative phase reads frames of the whole warp (same warp produced them)

    // ---- warp-cooperative atom phase: tasks k = it*32+lane over (rho=k/24, a=k%24) ----
    // Output address = warpbase*72 + 3k + j  -> 32 lanes cover a contiguous 384B window.
    {
        const int wbase = warp * 32;
        const long resBase = (long)blockIdx.x * BT + wbase;
        float* owarp = out + resBase * 72;

        int a   = (lane < 24) ? lane : lane - 24;
        int rho = (lane < 24) ? 0 : 1;

        #pragma unroll
        for (int it = 0; it < 24; ++it) {
            const int trho = wbase + rho;
            const int rtl  = s_rt[trho];
            const int rd   = (int)s_rdep8[a * 21 + rtl];
            float4 q0 = s_opr[(rd*3+0)*PAD + trho];
            float4 q1 = s_opr[(rd*3+1)*PAD + trho];
            float4 q2 = s_opr[(rd*3+2)*PAD + trho];
            const float v0 = s_rig[(a*3+0) * 21 + rtl];
            const float v1 = s_rig[(a*3+1) * 21 + rtl];
            const float v2 = s_rig[(a*3+2) * 21 + rtl];
            if (resBase + rho < (long)nres) {
                float* p = owarp + rho * 72 + a * 3;
                p[0] = q0.x*v0 + q0.y*v1 + q0.z*v2 + q2.y;
                p[1] = q0.w*v0 + q1.x*v1 + q1.y*v2 + q2.z;
                p[2] = q1.z*v0 + q1.w*v1 + q2.x*v2 + q2.w;
            }
            // advance task index k by 32:  a += 8 (mod 24), rho gets the carry
            a += 8; rho += 1;
            if (a >= 24) { a -= 24; rho += 1; }
        }
    }

    // ---- second output: opr[:,0] (read from smem frame 0), coalesced ----
    {
        const int wbase = warp * 32;
        const long resBase = (long)blockIdx.x * BT + wbase;
        long rem = (long)nres - resBase;
        const int cnt = (rem >= 32) ? 32 : (rem > 0 ? (int)rem : 0);
        float* o2 = out + (long)nres * 72 + resBase * 12;
        const int tot = cnt * 12;
        for (int k = lane; k < tot; k += 32) {
            const int l = k / 12;
            const int c = k - l * 12;
            const float* sp = (const float*)&s_opr[(c >> 2) * PAD + wbase + l];
            o2[k] = sp[c & 3];
        }
    }
}

extern "C" void kernel_launch(void* const* d_in, const int* in_sizes, int n_in,
                              void* d_out, int out_size)
{
    const int*   rtype   = (const int*)  d_in[0];
    const float* bb      = (const float*)d_in[1];
    const float* pos0    = (const float*)d_in[2];
    const float* sc      = (const float*)d_in[3];
    const float* g_trans = (const float*)d_in[4];
    const float* g_rig   = (const float*)d_in[5];
    const int*   g_tdep  = (const int*)  d_in[6];
    const int*   g_rdep  = (const int*)  d_in[7];
    float* out = (float*)d_out;

    const int nres = in_sizes[0];

    cudaFuncSetAttribute(backbone_kernel,
                         cudaFuncAttributeMaxDynamicSharedMemorySize, SMEM_BYTES);

    const int grid = (nres + BT - 1) / BT;
    backbone_kernel<<<grid, BT, SMEM_BYTES>>>(rtype, bb, pos0, sc,
                                              g_trans, g_rig, g_tdep, g_rdep,
                                              out, nres);
}

// round 9
// speedup vs baseline: 2.0772x; 1.3205x over previous
#include <cuda_runtime.h>
#include <cuda_fp16.h>

// N=524288 residues, 21 residue types, 8 rigid frames, 24 atoms.
static constexpr int BT = 256;     // threads per block (1 thread = 1 residue in build phase)
static constexpr int W  = BT + 1;  // half2-row stride for frame store (257 ≡ 1 mod 32 -> conflict-free)

// Shared memory layout (word offsets)
static constexpr int S_TRANS = 0;                   // 96*21 floats, transposed [comp][rt]
static constexpr int S_RIG   = S_TRANS + 96 * 21;   // 72*21 floats, transposed [comp][rt]
static constexpr int S_RT    = S_RIG   + 72 * 21;   // BT ints
static constexpr int S_TDEPP = S_RT    + BT;        // 2*21 u32 (packed tdep bytes, [rt*2+half])
static constexpr int S_RDEP8 = S_TDEPP + 2 * 21;    // 24*21 bytes = 126 words, [a*21+rt]
static constexpr int S_OPRH  = S_RDEP8 + 126;       // 48 rows * W half2 (frames, fp16x2)
static constexpr int SMEM_WORDS = S_OPRH + 48 * W;
static constexpr int SMEM_BYTES = SMEM_WORDS * 4;   // 65,152 B; occupancy reg-bound at 2 blocks

__global__ void __launch_bounds__(BT, 2)
backbone_kernel(const int* __restrict__ rtype,
                const float* __restrict__ bb,       // (N,4,3)
                const float* __restrict__ pos0,     // (N,3)
                const float* __restrict__ sc,       // (N,7,2)
                const float* __restrict__ g_trans,  // (21,8,4,3)
                const float* __restrict__ g_rig,    // (21,24,3)
                const int* __restrict__ g_tdep,     // (21,8)
                const int* __restrict__ g_rdep,     // (21,24)
                float* __restrict__ out, int nres)
{
    extern __shared__ float sm[];
    float*         s_trans = sm + S_TRANS;
    float*         s_rig   = sm + S_RIG;
    int*           s_rt    = (int*)(sm + S_RT);
    unsigned*      s_tdepp = (unsigned*)(sm + S_TDEPP);
    unsigned char* s_rdep8 = (unsigned char*)(sm + S_RDEP8);
    __half2*       s_oprh  = (__half2*)(sm + S_OPRH);  // index: (frame*6 + pair)*W + tid

    const int tid  = threadIdx.x;
    const int lane = tid & 31;
    const int warp = tid >> 5;

    // ---- stage tables (transposed: stride-21 -> conflict-free divergent-rt reads) ----
    for (int i = tid; i < 96 * 21; i += BT) s_trans[(i % 96) * 21 + i / 96] = g_trans[i];
    for (int i = tid; i < 72 * 21; i += BT) s_rig  [(i % 72) * 21 + i / 72] = g_rig[i];
    for (int i = tid; i < 24 * 21; i += BT) s_rdep8[(i % 24) * 21 + i / 24] = (unsigned char)g_rdep[i];
    for (int i = tid; i < 2 * 21;  i += BT) {
        const int rtt = i >> 1, h = i & 1;
        unsigned wv = 0;
        #pragma unroll
        for (int b = 0; b < 4; b++)
            wv |= ((unsigned)g_tdep[rtt * 8 + h * 4 + b] & 0xFFu) << (8 * b);
        s_tdepp[i] = wv;
    }
    __syncthreads();

    const int n  = blockIdx.x * BT + tid;
    const int nc = (n < nres) ? n : (nres - 1);   // clamp loads; stores gated later
    const int rt = rtype[nc];
    s_rt[tid] = rt;

    const unsigned dlo = s_tdepp[rt * 2 + 0];
    const unsigned dhi = s_tdepp[rt * 2 + 1];

    // ---- per-residue inputs ----
    const float4* bb4 = (const float4*)bb + (size_t)nc * 3;
    float4 b0 = bb4[0], b1 = bb4[1], b2 = bb4[2];
    const float Y00=b0.x, Y01=b0.y, Y02=b0.z;
    const float Y10=b0.w, Y11=b1.x, Y12=b1.y;
    const float Y20=b1.z, Y21=b1.w, Y22=b2.x;
    const float l0 = b2.y + pos0[nc*3+0];
    const float l1 = b2.z + pos0[nc*3+1];
    const float l2 = b2.w + pos0[nc*3+2];
    const float2* sc2 = (const float2*)sc + (size_t)nc * 7;

    // ---- register-resident fp32 frames ----
    float f[8][12];

    // frame 0: combine(T[rt][0], opr0)
    {
        float X[12];
        #pragma unroll
        for (int c = 0; c < 12; c++) X[c] = s_trans[c * 21 + rt];
        f[0][0] = X[0]*Y00 + X[1]*Y10 + X[2]*Y20;
        f[0][1] = X[0]*Y01 + X[1]*Y11 + X[2]*Y21;
        f[0][2] = X[0]*Y02 + X[1]*Y12 + X[2]*Y22;
        f[0][3] = X[3]*Y00 + X[4]*Y10 + X[5]*Y20;
        f[0][4] = X[3]*Y01 + X[4]*Y11 + X[5]*Y21;
        f[0][5] = X[3]*Y02 + X[4]*Y12 + X[5]*Y22;
        f[0][6] = X[6]*Y00 + X[7]*Y10 + X[8]*Y20;
        f[0][7] = X[6]*Y01 + X[7]*Y11 + X[8]*Y21;
        f[0][8] = X[6]*Y02 + X[7]*Y12 + X[8]*Y22;
        f[0][9]  = X[0]*l0 + X[1]*l1 + X[2]*l2 + X[9];
        f[0][10] = X[3]*l0 + X[4]*l1 + X[5]*l2 + X[10];
        f[0][11] = X[6]*l0 + X[7]*l1 + X[8]*l2 + X[11];
        #pragma unroll
        for (int p = 0; p < 6; p++)
            s_oprh[(0*6 + p)*W + tid] = __floats2half2_rn(f[0][2*p], f[0][2*p+1]);
    }

    // frames 1..7: SEL-selected prev (exact fp32), single fp16 rounding at store
    #pragma unroll
    for (int r = 1; r < 8; r++) {
        const float2 cs = sc2[r-1];
        const float cc = cs.x, ss = cs.y;

        float Xr[12];
        #pragma unroll
        for (int c = 0; c < 12; c++) Xr[c] = s_trans[(r*12 + c) * 21 + rt];

        // A = T[rt][r] composed with rot_x(c,s)   (translation unchanged)
        const float A0 = Xr[0], A1 = Xr[1]*cc + Xr[2]*ss, A2 = Xr[2]*cc - Xr[1]*ss;
        const float A3 = Xr[3], A4 = Xr[4]*cc + Xr[5]*ss, A5 = Xr[5]*cc - Xr[4]*ss;
        const float A6 = Xr[6], A7 = Xr[7]*cc + Xr[8]*ss, A8 = Xr[8]*cc - Xr[7]*ss;
        const float At0 = Xr[9], At1 = Xr[10], At2 = Xr[11];

        const int dep = (int)(((r < 4 ? dlo : dhi) >> ((r & 3) * 8)) & 0xFFu);

        float P[12];
        #pragma unroll
        for (int k = 0; k < 12; k++) P[k] = f[0][k];
        #pragma unroll
        for (int j = 1; j < 8; j++) {
            if (j < r) {                 // compile-time prune
                const bool m = (dep == j);
                #pragma unroll
                for (int k = 0; k < 12; k++) P[k] = m ? f[j][k] : P[k];
            }
        }

        f[r][0] = P[0]*A0 + P[1]*A3 + P[2]*A6;
        f[r][1] = P[0]*A1 + P[1]*A4 + P[2]*A7;
        f[r][2] = P[0]*A2 + P[1]*A5 + P[2]*A8;
        f[r][3] = P[3]*A0 + P[4]*A3 + P[5]*A6;
        f[r][4] = P[3]*A1 + P[4]*A4 + P[5]*A7;
        f[r][5] = P[3]*A2 + P[4]*A5 + P[5]*A8;
        f[r][6] = P[6]*A0 + P[7]*A3 + P[8]*A6;
        f[r][7] = P[6]*A1 + P[7]*A4 + P[8]*A7;
        f[r][8] = P[6]*A2 + P[7]*A5 + P[8]*A8;
        f[r][9]  = P[0]*At0 + P[1]*At1 + P[2]*At2 + P[9];
        f[r][10] = P[3]*At0 + P[4]*At1 + P[5]*At2 + P[10];
        f[r][11] = P[6]*At0 + P[7]*At1 + P[8]*At2 + P[11];

        #pragma unroll
        for (int p = 0; p < 6; p++)
            s_oprh[(r*6 + p)*W + tid] = __floats2half2_rn(f[r][2*p], f[r][2*p+1]);
    }

    __syncwarp();   // atom phase reads frames of the whole warp (this warp produced them)

    // ---- warp-cooperative atom phase: task k = it*32+lane, (rho=k/24, a=k%24) ----
    // Output addr = warpbase*72 + 3k + j -> 32 lanes span a contiguous 384B window.
    {
        const int wbase = warp * 32;
        const long resBase = (long)blockIdx.x * BT + wbase;
        float* owarp = out + resBase * 72;

        int a   = (lane < 24) ? lane : lane - 24;
        int rho = (lane < 24) ? 0 : 1;

        #pragma unroll
        for (int it = 0; it < 24; ++it) {
            const int trho = wbase + rho;
            const int rtl  = s_rt[trho];
            const int rd   = (int)s_rdep8[a * 21 + rtl];

            float m[12];
            #pragma unroll
            for (int p = 0; p < 6; p++) {
                float2 v = __half22float2(s_oprh[(rd*6 + p)*W + trho]);
                m[2*p] = v.x; m[2*p+1] = v.y;
            }
            const float v0 = s_rig[(a*3+0) * 21 + rtl];
            const float v1 = s_rig[(a*3+1) * 21 + rtl];
            const float v2 = s_rig[(a*3+2) * 21 + rtl];
            if (resBase + rho < (long)nres) {
                float* p = owarp + rho * 72 + a * 3;
                p[0] = m[0]*v0 + m[1]*v1 + m[2]*v2 + m[9];
                p[1] = m[3]*v0 + m[4]*v1 + m[5]*v2 + m[10];
                p[2] = m[6]*v0 + m[7]*v1 + m[8]*v2 + m[11];
            }
            // advance k by 32: a += 8 (mod 24), rho takes the carry
            a += 8; rho += 1;
            if (a >= 24) { a -= 24; rho += 1; }
        }
    }

    // ---- second output: opr[:,0] (frame 0), coalesced ----
    {
        const int wbase = warp * 32;
        const long resBase = (long)blockIdx.x * BT + wbase;
        long rem = (long)nres - resBase;
        const int cnt = (rem >= 32) ? 32 : (rem > 0 ? (int)rem : 0);
        float* o2 = out + (long)nres * 72 + resBase * 12;
        const int tot = cnt * 12;
        for (int k = lane; k < tot; k += 32) {
            const int l = k / 12;
            const int c = k - l * 12;
            float2 v = __half22float2(s_oprh[(c >> 1)*W + wbase + l]);
            o2[k] = (c & 1) ? v.y : v.x;
        }
    }
}

extern "C" void kernel_launch(void* const* d_in, const int* in_sizes, int n_in,
                              void* d_out, int out_size)
{
    const int*   rtype   = (const int*)  d_in[0];
    const float* bb      = (const float*)d_in[1];
    const float* pos0    = (const float*)d_in[2];
    const float* sc      = (const float*)d_in[3];
    const float* g_trans = (const float*)d_in[4];
    const float* g_rig   = (const float*)d_in[5];
    const int*   g_tdep  = (const int*)  d_in[6];
    const int*   g_rdep  = (const int*)  d_in[7];
    float* out = (float*)d_out;

    const int nres = in_sizes[0];

    cudaFuncSetAttribute(backbone_kernel,
                         cudaFuncAttributeMaxDynamicSharedMemorySize, SMEM_BYTES);

    const int grid = (nres + BT - 1) / BT;
    backbone_kernel<<<grid, BT, SMEM_BYTES>>>(rtype, bb, pos0, sc,
                                              g_trans, g_rig, g_tdep, g_rdep,
                                              out, nres);
}